// round 7
// baseline (speedup 1.0000x reference)
#include <cuda_runtime.h>
#include <cuda_bf16.h>
#include <cstddef>
#include <cstdint>

// Problem constants
#define H      1024
#define BSZ    4
#define TLEN   1024
#define G4H    4096          // 4*H
#define NTOK   4096          // BSZ*TLEN
#define VOCAB  32000

// Recurrent kernel config
#define NCTA_R 128
#define TPB_R  256
#define UPC    8             // hidden units per CTA (H / NCTA_R)
#define RPC    32            // gate rows per CTA (4*UPC)
#define WPAD   1028          // padded row stride for Whh slice in smem

// GEMM config
#define BM 128
#define BN 128
#define BK 32
#define SROW 40              // padded bf16 row stride in smem (80B, ldsm conflict-free)
#define OFF_AH 0
#define OFF_AL 10240
#define OFF_BH 20480
#define OFF_BL 30720
#define SBYTES 40960         // one stage: 4 tiles * 128*40*2 B
#define GSMEM  (2 * SBYTES)

// Scratch (device globals; no allocations allowed)
__device__ float g_pre[(size_t)NTOK * G4H];
__device__ __nv_bfloat16 g_xh[(size_t)NTOK * H];   // activation hi (embed out / hs out)
__device__ __nv_bfloat16 g_xl[(size_t)NTOK * H];   // activation lo
__device__ __nv_bfloat16 g_wh[(size_t)VOCAB * H];  // weight hi (Wih or Wproj)
__device__ __nv_bfloat16 g_wl[(size_t)VOCAB * H];  // weight lo
__device__ float g_h[BSZ * H];
__device__ int g_bar_count;   // returns to 0 every launch (deterministic replays)
__device__ int g_bar_flag;    // toggled an even # of times per launch -> returns to 0

// ---------------------------------------------------------------------------
// Split fp32 -> bf16 hi/lo
// ---------------------------------------------------------------------------
__device__ __forceinline__ void split1(float v, __nv_bfloat16& hi, __nv_bfloat16& lo) {
    hi = __float2bfloat16(v);
    lo = __float2bfloat16(v - __bfloat162float(hi));
}

__global__ void split_kernel(const float* __restrict__ w,
                             __nv_bfloat16* __restrict__ hi,
                             __nv_bfloat16* __restrict__ lo, int n4)
{
    int i = blockIdx.x * blockDim.x + threadIdx.x;
    if (i >= n4) return;
    float4 v = __ldg(&((const float4*)w)[i]);
    __nv_bfloat16 h0, h1, h2, h3, l0, l1, l2, l3;
    split1(v.x, h0, l0); split1(v.y, h1, l1);
    split1(v.z, h2, l2); split1(v.w, h3, l3);
    __nv_bfloat162* H2 = (__nv_bfloat162*)(hi) + 2 * i;
    __nv_bfloat162* L2 = (__nv_bfloat162*)(lo) + 2 * i;
    H2[0] = __halves2bfloat162(h0, h1); H2[1] = __halves2bfloat162(h2, h3);
    L2[0] = __halves2bfloat162(l0, l1); L2[1] = __halves2bfloat162(l2, l3);
}

// ---------------------------------------------------------------------------
// Embedding gather + split: xh/xl[n,:] = split(emb[x[n],:])
// ---------------------------------------------------------------------------
__global__ void embed_split_kernel(const int* __restrict__ x,
                                   const float* __restrict__ emb,
                                   __nv_bfloat16* __restrict__ xh,
                                   __nv_bfloat16* __restrict__ xl)
{
    int n = blockIdx.x;
    int tok = __ldg(&x[n]);
    int i = threadIdx.x;                 // 0..255, 4 floats each
    float4 v = __ldg(&((const float4*)(emb + (size_t)tok * H))[i]);
    __nv_bfloat16 h0, h1, h2, h3, l0, l1, l2, l3;
    split1(v.x, h0, l0); split1(v.y, h1, l1);
    split1(v.z, h2, l2); split1(v.w, h3, l3);
    __nv_bfloat162* H2 = (__nv_bfloat162*)(xh + (size_t)n * H) + 2 * i;
    __nv_bfloat162* L2 = (__nv_bfloat162*)(xl + (size_t)n * H) + 2 * i;
    H2[0] = __halves2bfloat162(h0, h1); H2[1] = __halves2bfloat162(h2, h3);
    L2[0] = __halves2bfloat162(l0, l1); L2[1] = __halves2bfloat162(l2, l3);
}

// ---------------------------------------------------------------------------
// Tensor-core GEMM, split-bf16 3-term: C[M,N] = A*B^T + bias1 (+bias2)
//   A (hi/lo) : [M,K] row-major bf16;  B (hi/lo) : [N,K] row-major bf16
//   C = Ah*Bh + Ah*Bl + Al*Bh   (fp32 accumulate, ~2^-17 product error)
// 128x128x32 CTA tile, 8 warps (4x2), warp tile 32x64, cp.async 2-stage.
// gridDim.x = M/128 (fastest) so concurrent CTAs share B tiles in L2.
// ---------------------------------------------------------------------------
__device__ __forceinline__ void cp16(uint32_t s, const void* g) {
    asm volatile("cp.async.cg.shared.global [%0], [%1], 16;" :: "r"(s), "l"(g));
}
__device__ __forceinline__ void cp_commit() {
    asm volatile("cp.async.commit_group;");
}
__device__ __forceinline__ void ldsm4(uint32_t* r, uint32_t addr) {
    asm volatile("ldmatrix.sync.aligned.m8n8.x4.shared.b16 {%0,%1,%2,%3}, [%4];"
                 : "=r"(r[0]), "=r"(r[1]), "=r"(r[2]), "=r"(r[3]) : "r"(addr));
}
__device__ __forceinline__ void mma_bf16(float* c, const uint32_t* a, const uint32_t* b) {
    asm volatile("mma.sync.aligned.m16n8k16.row.col.f32.bf16.bf16.f32 "
                 "{%0,%1,%2,%3},{%4,%5,%6,%7},{%8,%9},{%0,%1,%2,%3};"
                 : "+f"(c[0]), "+f"(c[1]), "+f"(c[2]), "+f"(c[3])
                 : "r"(a[0]), "r"(a[1]), "r"(a[2]), "r"(a[3]), "r"(b[0]), "r"(b[1]));
}

__global__ __launch_bounds__(256)
void gemm_bs(const __nv_bfloat16* __restrict__ Ah, const __nv_bfloat16* __restrict__ Al,
             const __nv_bfloat16* __restrict__ Bh, const __nv_bfloat16* __restrict__ Bl,
             const float* __restrict__ bias1, const float* __restrict__ bias2,
             float* __restrict__ C, int M, int N, int K)
{
    extern __shared__ __nv_bfloat16 smem_bf[];
    const int tid  = threadIdx.x;
    const int lane = tid & 31;
    const int warp = tid >> 5;
    const int wm   = warp & 3;       // 0..3  (M)
    const int wn   = warp >> 2;      // 0..1  (N)
    const int bm   = blockIdx.x * BM;
    const int bn   = blockIdx.y * BN;
    const int KIT  = K / BK;

    const uint32_t sbase = (uint32_t)__cvta_generic_to_shared(smem_bf);

    // loader: thread -> (row 0..127, 32B half), 2 cp16 per tile
    const int lrow  = tid >> 1;
    const int lhalf = tid & 1;
    const __nv_bfloat16* gAh = Ah + (size_t)(bm + lrow) * K + lhalf * 16;
    const __nv_bfloat16* gAl = Al + (size_t)(bm + lrow) * K + lhalf * 16;
    const __nv_bfloat16* gBh = Bh + (size_t)(bn + lrow) * K + lhalf * 16;
    const __nv_bfloat16* gBl = Bl + (size_t)(bn + lrow) * K + lhalf * 16;
    const uint32_t srow = sbase + (uint32_t)(lrow * SROW + lhalf * 16) * 2;

#define LOAD_STAGE(stage, kb)                                                  \
    do {                                                                       \
        uint32_t s_ = srow + (stage) * SBYTES;                                 \
        size_t go_ = (size_t)(kb) * BK;                                        \
        cp16(s_ + OFF_AH,      gAh + go_);                                     \
        cp16(s_ + OFF_AH + 16, gAh + go_ + 8);                                 \
        cp16(s_ + OFF_AL,      gAl + go_);                                     \
        cp16(s_ + OFF_AL + 16, gAl + go_ + 8);                                 \
        cp16(s_ + OFF_BH,      gBh + go_);                                     \
        cp16(s_ + OFF_BH + 16, gBh + go_ + 8);                                 \
        cp16(s_ + OFF_BL,      gBl + go_);                                     \
        cp16(s_ + OFF_BL + 16, gBl + go_ + 8);                                 \
    } while (0)

    float acc[2][8][4];
#pragma unroll
    for (int mt = 0; mt < 2; mt++)
#pragma unroll
        for (int nt = 0; nt < 8; nt++)
#pragma unroll
            for (int r = 0; r < 4; r++) acc[mt][nt][r] = 0.f;

    // ldmatrix lane address pattern
    const int lr8 = (lane & 7) + ((lane >> 3) & 1) * 8;  // row within 16
    const int lc8 = ((lane >> 4) & 1) * 8;               // k-half 0/8

    LOAD_STAGE(0, 0); cp_commit();
    LOAD_STAGE(1, 1); cp_commit();

    for (int kb = 0; kb < KIT; kb++) {
        if (kb + 1 < KIT) { asm volatile("cp.async.wait_group 1;"); }
        else              { asm volatile("cp.async.wait_group 0;"); }
        __syncthreads();

        const uint32_t sb = sbase + (kb & 1) * SBYTES;
#pragma unroll
        for (int kk = 0; kk < BK; kk += 16) {
            uint32_t ah[2][4], al[2][4], bh[8][2], bl[8][2];
#pragma unroll
            for (int mt = 0; mt < 2; mt++) {
                uint32_t aoff = (uint32_t)((wm * 32 + mt * 16 + lr8) * SROW + kk + lc8) * 2;
                ldsm4(ah[mt], sb + OFF_AH + aoff);
                ldsm4(al[mt], sb + OFF_AL + aoff);
            }
#pragma unroll
            for (int bt = 0; bt < 4; bt++) {
                uint32_t boff = (uint32_t)((wn * 64 + bt * 16 + lr8) * SROW + kk + lc8) * 2;
                uint32_t r[4];
                ldsm4(r, sb + OFF_BH + boff);
                bh[2*bt][0] = r[0]; bh[2*bt][1] = r[2];
                bh[2*bt+1][0] = r[1]; bh[2*bt+1][1] = r[3];
                ldsm4(r, sb + OFF_BL + boff);
                bl[2*bt][0] = r[0]; bl[2*bt][1] = r[2];
                bl[2*bt+1][0] = r[1]; bl[2*bt+1][1] = r[3];
            }
#pragma unroll
            for (int mt = 0; mt < 2; mt++)
#pragma unroll
                for (int nt = 0; nt < 8; nt++) {
                    mma_bf16(acc[mt][nt], ah[mt], bh[nt]);
                    mma_bf16(acc[mt][nt], ah[mt], bl[nt]);
                    mma_bf16(acc[mt][nt], al[mt], bh[nt]);
                }
        }
        __syncthreads();
        if (kb + 2 < KIT) { LOAD_STAGE(kb & 1, kb + 2); cp_commit(); }
    }

    // epilogue
    const int g  = lane >> 2;
    const int tc = lane & 3;
#pragma unroll
    for (int nt = 0; nt < 8; nt++) {
        int col = bn + wn * 64 + nt * 8 + tc * 2;
        float b0 = bias1 ? __ldg(&bias1[col])     : 0.f;
        float b1 = bias1 ? __ldg(&bias1[col + 1]) : 0.f;
        if (bias2) { b0 += __ldg(&bias2[col]); b1 += __ldg(&bias2[col + 1]); }
#pragma unroll
        for (int mt = 0; mt < 2; mt++) {
            int row0 = bm + wm * 32 + mt * 16 + g;
            float2 v0 = make_float2(acc[mt][nt][0] + b0, acc[mt][nt][1] + b1);
            float2 v1 = make_float2(acc[mt][nt][2] + b0, acc[mt][nt][3] + b1);
            *(float2*)&C[(size_t)row0 * N + col]       = v0;
            *(float2*)&C[(size_t)(row0 + 8) * N + col] = v1;
        }
    }
#undef LOAD_STAGE
}

// ---------------------------------------------------------------------------
// Persistent LSTM recurrence (unchanged math; now emits split-bf16 hs).
// ---------------------------------------------------------------------------
__global__ __launch_bounds__(TPB_R)
void lstm_recurrent(const float* __restrict__ pre,
                    const float* __restrict__ Whh,
                    __nv_bfloat16* __restrict__ hs_h,
                    __nv_bfloat16* __restrict__ hs_l)
{
    extern __shared__ float sm[];
    float* whh_s = sm;                       // RPC * WPAD
    float* h_s   = sm + RPC * WPAD;          // BSZ * H
    float* z_s   = h_s + BSZ * H;            // RPC * BSZ
    float* c_s   = z_s + RPC * BSZ;          // 32

    const int tid  = threadIdx.x;
    const int cta  = blockIdx.x;
    const int warp = tid >> 5;
    const int lane = tid & 31;

    for (int i = tid; i < RPC * H; i += TPB_R) {
        int r = i >> 10;
        int k = i & (H - 1);
        int q = r >> 3;
        int uu = r & 7;
        int grow = q * H + cta * UPC + uu;
        whh_s[r * WPAD + k] = __ldg(&Whh[(size_t)grow * H + k]);
    }
    if (tid < 32) c_s[tid] = 0.f;
    int sense = 0;
    __syncthreads();

    for (int t = 0; t < TLEN; t++) {
        float4* hs4 = (float4*)h_s;
        if (t == 0) {
            for (int i = tid; i < (BSZ * H) / 4; i += TPB_R)
                hs4[i] = make_float4(0.f, 0.f, 0.f, 0.f);
        } else {
            const float4* hg = (const float4*)g_h;
            for (int i = tid; i < (BSZ * H) / 4; i += TPB_R)
                hs4[i] = __ldcg(hg + i);
        }
        float p0 = 0.f, p1 = 0.f, p2 = 0.f, p3 = 0.f;
        int uu = 0, b = 0;
        if (tid < 32) {
            uu = tid >> 2; b = tid & 3;
            size_t base = ((size_t)(b * TLEN + t)) * G4H + cta * UPC + uu;
            p0 = __ldg(&pre[base]);
            p1 = __ldg(&pre[base + H]);
            p2 = __ldg(&pre[base + 2 * H]);
            p3 = __ldg(&pre[base + 3 * H]);
        }
        __syncthreads();

        float acc[4][4];
#pragma unroll
        for (int i = 0; i < 4; i++)
#pragma unroll
            for (int j = 0; j < 4; j++) acc[i][j] = 0.f;

        const int rbase = warp * 4;
#pragma unroll
        for (int p = 0; p < 8; p++) {
            int k = p * 128 + lane * 4;
            float4 h0 = *(const float4*)&h_s[k];
            float4 h1 = *(const float4*)&h_s[H + k];
            float4 h2 = *(const float4*)&h_s[2 * H + k];
            float4 h3 = *(const float4*)&h_s[3 * H + k];
#pragma unroll
            for (int i = 0; i < 4; i++) {
                float4 w = *(const float4*)&whh_s[(rbase + i) * WPAD + k];
                acc[i][0] += w.x*h0.x + w.y*h0.y + w.z*h0.z + w.w*h0.w;
                acc[i][1] += w.x*h1.x + w.y*h1.y + w.z*h1.z + w.w*h1.w;
                acc[i][2] += w.x*h2.x + w.y*h2.y + w.z*h2.z + w.w*h2.w;
                acc[i][3] += w.x*h3.x + w.y*h3.y + w.z*h3.z + w.w*h3.w;
            }
        }
#pragma unroll
        for (int i = 0; i < 4; i++)
#pragma unroll
            for (int j = 0; j < 4; j++) {
                float v = acc[i][j];
                v += __shfl_xor_sync(0xffffffffu, v, 16);
                v += __shfl_xor_sync(0xffffffffu, v, 8);
                v += __shfl_xor_sync(0xffffffffu, v, 4);
                v += __shfl_xor_sync(0xffffffffu, v, 2);
                v += __shfl_xor_sync(0xffffffffu, v, 1);
                acc[i][j] = v;
            }
        if (lane == 0) {
#pragma unroll
            for (int i = 0; i < 4; i++)
#pragma unroll
                for (int j = 0; j < 4; j++)
                    z_s[(rbase + i) * 4 + j] = acc[i][j];
        }
        __syncthreads();

        if (tid < 32) {
            float zi = z_s[uu * 4 + b] + p0;
            float zf = z_s[(8 + uu) * 4 + b] + p1;
            float zg = z_s[(16 + uu) * 4 + b] + p2;
            float zo = z_s[(24 + uu) * 4 + b] + p3;
            float ig = 1.f / (1.f + __expf(-zi));
            float fg = 1.f / (1.f + __expf(-zf));
            float gg = tanhf(zg);
            float og = 1.f / (1.f + __expf(-zo));
            float c = fg * c_s[tid] + ig * gg;
            c_s[tid] = c;
            float hval = og * tanhf(c);
            int col = cta * UPC + uu;
            __stcg(&g_h[b * H + col], hval);
            size_t oidx = ((size_t)(b * TLEN + t)) * H + col;
            __nv_bfloat16 hh, hl;
            split1(hval, hh, hl);
            hs_h[oidx] = hh;
            hs_l[oidx] = hl;
        }
        __syncthreads();

        // grid-wide sense-reversing barrier (128 resident CTAs)
        if (tid == 0) {
            sense ^= 1;
            int prev;
            asm volatile("atom.add.acq_rel.gpu.s32 %0, [%1], 1;"
                         : "=r"(prev) : "l"(&g_bar_count) : "memory");
            if (prev == NCTA_R - 1) {
                asm volatile("st.relaxed.gpu.s32 [%0], %1;"
                             :: "l"(&g_bar_count), "r"(0) : "memory");
                asm volatile("st.release.gpu.s32 [%0], %1;"
                             :: "l"(&g_bar_flag), "r"(sense) : "memory");
            } else {
                int f;
                do {
                    asm volatile("ld.acquire.gpu.s32 %0, [%1];"
                                 : "=r"(f) : "l"(&g_bar_flag) : "memory");
                } while (f != sense);
            }
        }
        __syncthreads();
    }
}

// ---------------------------------------------------------------------------
// Host launcher (graph-capturable: kernels only)
// ---------------------------------------------------------------------------
extern "C" void kernel_launch(void* const* d_in, const int* in_sizes, int n_in,
                              void* d_out, int out_size)
{
    (void)in_sizes; (void)n_in; (void)out_size;
    const int*   x     = (const int*)  d_in[0];
    const float* emb   = (const float*)d_in[1];
    const float* Wproj = (const float*)d_in[2];
    const float* bproj = (const float*)d_in[3];
    const float* Wih0  = (const float*)d_in[4];
    const float* Whh0  = (const float*)d_in[5];
    const float* bih0  = (const float*)d_in[6];
    const float* bhh0  = (const float*)d_in[7];
    const float* Wih1  = (const float*)d_in[8];
    const float* Whh1  = (const float*)d_in[9];
    const float* bih1  = (const float*)d_in[10];
    const float* bhh1  = (const float*)d_in[11];
    float* out = (float*)d_out;

    float *pre;
    __nv_bfloat16 *xh, *xl, *wh, *wl;
    cudaGetSymbolAddress((void**)&pre, g_pre);
    cudaGetSymbolAddress((void**)&xh, g_xh);
    cudaGetSymbolAddress((void**)&xl, g_xl);
    cudaGetSymbolAddress((void**)&wh, g_wh);
    cudaGetSymbolAddress((void**)&wl, g_wl);

    const int RSMEM = (RPC * WPAD + BSZ * H + RPC * BSZ + 32) * 4;
    cudaFuncSetAttribute(lstm_recurrent,
                         cudaFuncAttributeMaxDynamicSharedMemorySize, RSMEM);
    cudaFuncSetAttribute(gemm_bs,
                         cudaFuncAttributeMaxDynamicSharedMemorySize, GSMEM);

    const int WIH_N4 = (G4H * H) / 4;
    const int WPR_N4 = (VOCAB * H) / 4;

    // 1) embedding (split bf16 activations)
    embed_split_kernel<<<NTOK, 256>>>(x, emb, xh, xl);

    // 2) layer 0
    split_kernel<<<(WIH_N4 + 255) / 256, 256>>>(Wih0, wh, wl, WIH_N4);
    {
        dim3 g(NTOK / BM, G4H / BN);
        gemm_bs<<<g, 256, GSMEM>>>(xh, xl, wh, wl, bih0, bhh0, pre, NTOK, G4H, H);
    }
    lstm_recurrent<<<NCTA_R, TPB_R, RSMEM>>>(pre, Whh0, xh, xl);

    // 3) layer 1
    split_kernel<<<(WIH_N4 + 255) / 256, 256>>>(Wih1, wh, wl, WIH_N4);
    {
        dim3 g(NTOK / BM, G4H / BN);
        gemm_bs<<<g, 256, GSMEM>>>(xh, xl, wh, wl, bih1, bhh1, pre, NTOK, G4H, H);
    }
    lstm_recurrent<<<NCTA_R, TPB_R, RSMEM>>>(pre, Whh1, xh, xl);

    // 4) projection
    split_kernel<<<(WPR_N4 + 255) / 256, 256>>>(Wproj, wh, wl, WPR_N4);
    {
        dim3 g(NTOK / BM, VOCAB / BN);   // m fastest -> B tiles shared in L2
        gemm_bs<<<g, 256, GSMEM>>>(xh, xl, wh, wl, bproj, nullptr, out, NTOK, VOCAB, H);
    }
}

// round 8
// speedup vs baseline: 1.2199x; 1.2199x over previous
#include <cuda_runtime.h>
#include <cstddef>

// Problem constants
#define H      1024
#define BSZ    4
#define TLEN   1024
#define G4H    4096          // 4*H
#define NTOK   4096          // BSZ*TLEN
#define VOCAB  32000

// Recurrent kernel config
#define NCTA_R 128
#define TPB_R  256
#define UPC    8             // hidden units per CTA (H / NCTA_R)
#define RPC    32            // gate rows per CTA (4*UPC)
#define WPAD   1028          // padded row stride for Whh slice in smem

// Scratch (device globals; no allocations allowed)
__device__ float g_act[(size_t)NTOK * H];
__device__ float g_pre[(size_t)NTOK * G4H];
__device__ float g_hs0[(size_t)NTOK * H];
__device__ float g_hs1[(size_t)NTOK * H];
__device__ float g_h[2 * BSZ * H];       // double-buffered by step parity
__device__ int g_cnt0[8 * 64];           // level-0 counters, 256B apart; return to 0
__device__ int g_cnt1;                   // root counter; returns to 0
__device__ int g_bar_flag;               // toggled an even # of times -> returns to 0

// ---------------------------------------------------------------------------
// Packed fp32x2 helpers (FFMA2)
// ---------------------------------------------------------------------------
__device__ __forceinline__ unsigned long long pk2(float x, float y) {
    unsigned long long r;
    asm("mov.b64 %0, {%1, %2};" : "=l"(r) : "f"(x), "f"(y));
    return r;
}
__device__ __forceinline__ void ffma2(unsigned long long& d,
                                      unsigned long long a,
                                      unsigned long long b) {
    asm("fma.rn.f32x2 %0, %1, %2, %0;" : "+l"(d) : "l"(a), "l"(b));
}
__device__ __forceinline__ float2 upk2(unsigned long long v) {
    float2 f;
    asm("mov.b64 {%0, %1}, %2;" : "=f"(f.x), "=f"(f.y) : "l"(v));
    return f;
}

// ---------------------------------------------------------------------------
// Embedding gather: out[n, :] = emb[x[n], :]
// ---------------------------------------------------------------------------
__global__ void embed_kernel(const int* __restrict__ x,
                             const float* __restrict__ emb,
                             float* __restrict__ out)
{
    int n = blockIdx.x;
    int tok = __ldg(&x[n]);
    const float4* src = (const float4*)(emb + (size_t)tok * H);
    float4* dst = (float4*)(out + (size_t)n * H);
    dst[threadIdx.x] = __ldg(&src[threadIdx.x]);
}

// ---------------------------------------------------------------------------
// SGEMM: C[M,N] = A[M,K] * B[N,K]^T + bias1[N] (+ bias2[N])   (R6 version)
// ---------------------------------------------------------------------------
__global__ __launch_bounds__(256, 2)
void sgemm_abt(const float* __restrict__ A, const float* __restrict__ B,
               const float* __restrict__ bias1, const float* __restrict__ bias2,
               float* __restrict__ C, int M, int N, int K)
{
    __shared__ float As[16][132];
    __shared__ float Bs[16][132];
    const int tid = threadIdx.x;
    const int bm = blockIdx.y * 128;
    const int bn = blockIdx.x * 128;
    const int tx = tid & 15;
    const int ty = tid >> 4;
    const int lr = tid >> 2;          // 0..63
    const int lk = (tid & 3) << 2;    // 0,4,8,12

    const float* Ag = A + (size_t)(bm + lr) * K + lk;
    const float* Bg = B + (size_t)(bn + lr) * K + lk;

    unsigned long long acc2[4][8];
#pragma unroll
    for (int i = 0; i < 4; i++)
#pragma unroll
        for (int j = 0; j < 8; j++) acc2[i][j] = 0ull;

    float4 a0 = *(const float4*)(Ag);
    float4 a1 = *(const float4*)(Ag + (size_t)64 * K);
    float4 b0 = *(const float4*)(Bg);
    float4 b1 = *(const float4*)(Bg + (size_t)64 * K);

    for (int k0 = 0; k0 < K; k0 += 16) {
        __syncthreads();
        As[lk+0][lr]    = a0.x; As[lk+1][lr]    = a0.y; As[lk+2][lr]    = a0.z; As[lk+3][lr]    = a0.w;
        As[lk+0][lr+64] = a1.x; As[lk+1][lr+64] = a1.y; As[lk+2][lr+64] = a1.z; As[lk+3][lr+64] = a1.w;
        Bs[lk+0][lr]    = b0.x; Bs[lk+1][lr]    = b0.y; Bs[lk+2][lr]    = b0.z; Bs[lk+3][lr]    = b0.w;
        Bs[lk+0][lr+64] = b1.x; Bs[lk+1][lr+64] = b1.y; Bs[lk+2][lr+64] = b1.z; Bs[lk+3][lr+64] = b1.w;
        __syncthreads();
        if (k0 + 16 < K) {
            a0 = *(const float4*)(Ag + k0 + 16);
            a1 = *(const float4*)(Ag + (size_t)64 * K + k0 + 16);
            b0 = *(const float4*)(Bg + k0 + 16);
            b1 = *(const float4*)(Bg + (size_t)64 * K + k0 + 16);
        }
#pragma unroll
        for (int k = 0; k < 16; k++) {
            float4 aA = *(const float4*)&As[k][ty * 4];
            float4 aB = *(const float4*)&As[k][64 + ty * 4];
            float4 bA = *(const float4*)&Bs[k][tx * 4];
            float4 bB = *(const float4*)&Bs[k][64 + tx * 4];
            unsigned long long av2[4];
            av2[0] = pk2(aA.x, aA.y);
            av2[1] = pk2(aA.z, aA.w);
            av2[2] = pk2(aB.x, aB.y);
            av2[3] = pk2(aB.z, aB.w);
            unsigned long long bv2[8];
            bv2[0] = pk2(bA.x, bA.x);
            bv2[1] = pk2(bA.y, bA.y);
            bv2[2] = pk2(bA.z, bA.z);
            bv2[3] = pk2(bA.w, bA.w);
            bv2[4] = pk2(bB.x, bB.x);
            bv2[5] = pk2(bB.y, bB.y);
            bv2[6] = pk2(bB.z, bB.z);
            bv2[7] = pk2(bB.w, bB.w);
#pragma unroll
            for (int i = 0; i < 4; i++)
#pragma unroll
                for (int j = 0; j < 8; j++)
                    ffma2(acc2[i][j], av2[i], bv2[j]);
        }
    }

    float acc[8][8];
#pragma unroll
    for (int i2 = 0; i2 < 4; i2++)
#pragma unroll
        for (int j = 0; j < 8; j++) {
            float2 v = upk2(acc2[i2][j]);
            acc[2 * i2][j]     = v.x;
            acc[2 * i2 + 1][j] = v.y;
        }

    float bb[8];
#pragma unroll
    for (int jh = 0; jh < 2; jh++)
#pragma unroll
        for (int j = 0; j < 4; j++) {
            int n = bn + jh * 64 + tx * 4 + j;
            float v = bias1 ? __ldg(&bias1[n]) : 0.f;
            if (bias2) v += __ldg(&bias2[n]);
            bb[jh * 4 + j] = v;
        }
#pragma unroll
    for (int ih = 0; ih < 2; ih++)
#pragma unroll
        for (int i = 0; i < 4; i++) {
            int m = bm + ih * 64 + ty * 4 + i;
#pragma unroll
            for (int jh = 0; jh < 2; jh++) {
                float4 v;
                v.x = acc[ih*4+i][jh*4+0] + bb[jh*4+0];
                v.y = acc[ih*4+i][jh*4+1] + bb[jh*4+1];
                v.z = acc[ih*4+i][jh*4+2] + bb[jh*4+2];
                v.w = acc[ih*4+i][jh*4+3] + bb[jh*4+3];
                *(float4*)&C[(size_t)m * N + bn + jh * 64 + tx * 4] = v;
            }
        }
}

// ---------------------------------------------------------------------------
// Persistent LSTM recurrence. 128 resident CTAs, Whh slice pinned in SMEM.
// Grid barrier: two-level arrival tree (8 groups of 16 -> root of 8) with
// acq_rel RMWs, release flag publish, acquire polling. g_h double-buffered
// by step parity. Per-timestep hs store moved off the critical path.
// ---------------------------------------------------------------------------
__global__ __launch_bounds__(TPB_R)
void lstm_recurrent(const float* __restrict__ pre,
                    const float* __restrict__ Whh,
                    float* __restrict__ hs)
{
    extern __shared__ float sm[];
    float* whh_s = sm;                       // RPC * WPAD
    float* h_s   = sm + RPC * WPAD;          // BSZ * H
    float* z_s   = h_s + BSZ * H;            // RPC * BSZ
    float* c_s   = z_s + RPC * BSZ;          // 32

    const int tid  = threadIdx.x;
    const int cta  = blockIdx.x;
    const int warp = tid >> 5;
    const int lane = tid & 31;

    for (int i = tid; i < RPC * H; i += TPB_R) {
        int r = i >> 10;
        int k = i & (H - 1);
        int q = r >> 3;
        int uu = r & 7;
        int grow = q * H + cta * UPC + uu;
        whh_s[r * WPAD + k] = __ldg(&Whh[(size_t)grow * H + k]);
    }
    if (tid < 32) c_s[tid] = 0.f;
    int sense = 0;
    __syncthreads();

    for (int t = 0; t < TLEN; t++) {
        // h(t-1) into smem (zeros at t=0); read from parity buffer (t-1)&1
        float4* hs4 = (float4*)h_s;
        if (t == 0) {
            for (int i = tid; i < (BSZ * H) / 4; i += TPB_R)
                hs4[i] = make_float4(0.f, 0.f, 0.f, 0.f);
        } else {
            const float4* hg = (const float4*)(g_h + ((t - 1) & 1) * BSZ * H);
            for (int i = tid; i < (BSZ * H) / 4; i += TPB_R)
                hs4[i] = __ldcg(hg + i);
        }
        // prefetch pre-activations for gate threads
        float p0 = 0.f, p1 = 0.f, p2 = 0.f, p3 = 0.f;
        int uu = 0, b = 0;
        if (tid < 32) {
            uu = tid >> 2; b = tid & 3;
            size_t base = ((size_t)(b * TLEN + t)) * G4H + cta * UPC + uu;
            p0 = __ldg(&pre[base]);
            p1 = __ldg(&pre[base + H]);
            p2 = __ldg(&pre[base + 2 * H]);
            p3 = __ldg(&pre[base + 3 * H]);
        }
        __syncthreads();

        // z[r][b] = sum_k Whh_s[r][k] * h[b][k]; warp owns 4 rows, all 4 b.
        float acc[4][4];
#pragma unroll
        for (int i = 0; i < 4; i++)
#pragma unroll
            for (int j = 0; j < 4; j++) acc[i][j] = 0.f;

        const int rbase = warp * 4;
#pragma unroll
        for (int p = 0; p < 8; p++) {
            int k = p * 128 + lane * 4;
            float4 h0 = *(const float4*)&h_s[k];
            float4 h1 = *(const float4*)&h_s[H + k];
            float4 h2 = *(const float4*)&h_s[2 * H + k];
            float4 h3 = *(const float4*)&h_s[3 * H + k];
#pragma unroll
            for (int i = 0; i < 4; i++) {
                float4 w = *(const float4*)&whh_s[(rbase + i) * WPAD + k];
                acc[i][0] += w.x*h0.x + w.y*h0.y + w.z*h0.z + w.w*h0.w;
                acc[i][1] += w.x*h1.x + w.y*h1.y + w.z*h1.z + w.w*h1.w;
                acc[i][2] += w.x*h2.x + w.y*h2.y + w.z*h2.z + w.w*h2.w;
                acc[i][3] += w.x*h3.x + w.y*h3.y + w.z*h3.z + w.w*h3.w;
            }
        }
#pragma unroll
        for (int i = 0; i < 4; i++)
#pragma unroll
            for (int j = 0; j < 4; j++) {
                float v = acc[i][j];
                v += __shfl_xor_sync(0xffffffffu, v, 16);
                v += __shfl_xor_sync(0xffffffffu, v, 8);
                v += __shfl_xor_sync(0xffffffffu, v, 4);
                v += __shfl_xor_sync(0xffffffffu, v, 2);
                v += __shfl_xor_sync(0xffffffffu, v, 1);
                acc[i][j] = v;
            }
        if (lane == 0) {
#pragma unroll
            for (int i = 0; i < 4; i++)
#pragma unroll
                for (int j = 0; j < 4; j++)
                    z_s[(rbase + i) * 4 + j] = acc[i][j];
        }
        __syncthreads();

        // gates + state update (32 threads). Publish g_h only; hs deferred.
        float hval = 0.f;
        int col = 0;
        if (tid < 32) {
            float zi = z_s[uu * 4 + b] + p0;
            float zf = z_s[(8 + uu) * 4 + b] + p1;
            float zg = z_s[(16 + uu) * 4 + b] + p2;
            float zo = z_s[(24 + uu) * 4 + b] + p3;
            float ig = 1.f / (1.f + __expf(-zi));
            float fg = 1.f / (1.f + __expf(-zf));
            float gg = tanhf(zg);
            float og = 1.f / (1.f + __expf(-zo));
            float c = fg * c_s[tid] + ig * gg;
            c_s[tid] = c;
            hval = og * tanhf(c);
            col = cta * UPC + uu;
            __stcg(&g_h[(t & 1) * BSZ * H + b * H + col], hval);
        }
        __syncthreads();

        // two-level grid barrier: 8 groups x 16 CTAs -> root of 8.
        if (tid == 0) {
            sense ^= 1;
            int prev;
            int* c0 = &g_cnt0[(cta >> 4) * 64];
            asm volatile("atom.add.acq_rel.gpu.s32 %0, [%1], 1;"
                         : "=r"(prev) : "l"(c0) : "memory");
            bool root_done = false;
            if (prev == 15) {
                int p2v;
                asm volatile("atom.add.acq_rel.gpu.s32 %0, [%1], 1;"
                             : "=r"(p2v) : "l"(&g_cnt1) : "memory");
                if (p2v == 7) {
#pragma unroll
                    for (int gi = 0; gi < 8; gi++)
                        asm volatile("st.relaxed.gpu.s32 [%0], %1;"
                                     :: "l"(&g_cnt0[gi * 64]), "r"(0) : "memory");
                    asm volatile("st.relaxed.gpu.s32 [%0], %1;"
                                 :: "l"(&g_cnt1), "r"(0) : "memory");
                    asm volatile("st.release.gpu.s32 [%0], %1;"
                                 :: "l"(&g_bar_flag), "r"(sense) : "memory");
                    root_done = true;
                }
            }
            if (!root_done) {
                int f;
                do {
                    asm volatile("ld.acquire.gpu.s32 %0, [%1];"
                                 : "=r"(f) : "l"(&g_bar_flag) : "memory");
                } while (f != sense);
            }
        }
        __syncthreads();

        // off-critical-path: per-timestep hidden state output
        if (tid < 32)
            hs[((size_t)(b * TLEN + t)) * H + col] = hval;
    }
}

// ---------------------------------------------------------------------------
// Host launcher (graph-capturable: kernels only)
// ---------------------------------------------------------------------------
extern "C" void kernel_launch(void* const* d_in, const int* in_sizes, int n_in,
                              void* d_out, int out_size)
{
    (void)in_sizes; (void)n_in; (void)out_size;
    const int*   x     = (const int*)  d_in[0];
    const float* emb   = (const float*)d_in[1];
    const float* Wproj = (const float*)d_in[2];
    const float* bproj = (const float*)d_in[3];
    const float* Wih0  = (const float*)d_in[4];
    const float* Whh0  = (const float*)d_in[5];
    const float* bih0  = (const float*)d_in[6];
    const float* bhh0  = (const float*)d_in[7];
    const float* Wih1  = (const float*)d_in[8];
    const float* Whh1  = (const float*)d_in[9];
    const float* bih1  = (const float*)d_in[10];
    const float* bhh1  = (const float*)d_in[11];
    float* out = (float*)d_out;

    float *act, *pre, *hs0, *hs1;
    cudaGetSymbolAddress((void**)&act, g_act);
    cudaGetSymbolAddress((void**)&pre, g_pre);
    cudaGetSymbolAddress((void**)&hs0, g_hs0);
    cudaGetSymbolAddress((void**)&hs1, g_hs1);

    const int RSMEM = (RPC * WPAD + BSZ * H + RPC * BSZ + 32) * 4;
    cudaFuncSetAttribute(lstm_recurrent,
                         cudaFuncAttributeMaxDynamicSharedMemorySize, RSMEM);

    // 1) embedding
    embed_kernel<<<NTOK, 256>>>(x, emb, act);

    // 2) layer 0
    dim3 g1(G4H / 128, NTOK / 128);
    sgemm_abt<<<g1, 256>>>(act, Wih0, bih0, bhh0, pre, NTOK, G4H, H);
    lstm_recurrent<<<NCTA_R, TPB_R, RSMEM>>>(pre, Whh0, hs0);

    // 3) layer 1
    sgemm_abt<<<g1, 256>>>(hs0, Wih1, bih1, bhh1, pre, NTOK, G4H, H);
    lstm_recurrent<<<NCTA_R, TPB_R, RSMEM>>>(pre, Whh1, hs1);

    // 4) projection
    dim3 g2(VOCAB / 128, NTOK / 128);
    sgemm_abt<<<g2, 256>>>(hs1, Wproj, bproj, nullptr, out, NTOK, VOCAB, H);
}